// round 3
// baseline (speedup 1.0000x reference)
#include <cuda_runtime.h>
#include <math.h>

#define VSZ 30000
#define HSZ 512
#define BSZ 16
#define SSZ 256
#define JSZ 10
#define TSZ 8
#define NOPS 4
#define RSZ (JSZ*BSZ)
#define NEGV (-1e9f)

__device__ float g_w[RSZ*HSZ];
__device__ float g_hA[RSZ*HSZ];
__device__ float g_hB[RSZ*HSZ];
__device__ float g_part[4*RSZ*3072];
__device__ float g_logits[RSZ*VSZ];
__device__ float g_attn[RSZ*SSZ];
__device__ float g_ctx[RSZ*HSZ];
__device__ float g_pgen[RSZ];
__device__ float g_bval[RSZ];
__device__ int   g_bidx[RSZ];

__global__ __launch_bounds__(256)
void k_init(const float* __restrict__ slot, const float* __restrict__ ehid) {
    int i = blockIdx.x*blockDim.x + threadIdx.x;
    if (i < RSZ*HSZ) {
        int r = i / HSZ, h = i - r*HSZ;
        int j = r / BSZ, b = r - j*BSZ;
        g_w[i]  = slot[j*HSZ + h];
        g_hA[i] = ehid[b*HSZ + h];
    }
}

// grid (24,2,4) block 256: P[r,n] n<1536: w@Wih^T else h@Whh^T, split-K=4
__global__ __launch_bounds__(256)
void k_gru_gemm(const float* __restrict__ Wih,
                const float* __restrict__ Whh, int parity) {
    const float* __restrict__ hold = parity ? g_hB : g_hA;
    int n0 = blockIdx.x * 128, m0 = blockIdx.y * 80, z = blockIdx.z;
    const float* __restrict__ A  = (n0 < 1536) ? g_w : hold;
    const float* __restrict__ Bm = (n0 < 1536) ? Wih : Whh;
    int bc0 = (n0 < 1536) ? n0 : (n0 - 1536);
    __shared__ float As[32][81];
    __shared__ float Bs[32][129];
    int tid = threadIdx.x, tx = tid & 15, ty = tid >> 4;
    float acc[5][8];
    #pragma unroll
    for (int i = 0; i < 5; i++)
        #pragma unroll
        for (int j = 0; j < 8; j++) acc[i][j] = 0.f;
    for (int kt = 0; kt < 4; kt++) {
        int k0 = z*128 + kt*32;
        #pragma unroll
        for (int i = 0; i < 10; i++) {
            int idx = tid + 256*i; int m = idx >> 5, kk = idx & 31;
            As[kk][m] = A[(m0+m)*HSZ + k0 + kk];
        }
        #pragma unroll
        for (int i = 0; i < 16; i++) {
            int idx = tid + 256*i; int n = idx >> 5, kk = idx & 31;
            Bs[kk][n] = Bm[(bc0+n)*HSZ + k0 + kk];
        }
        __syncthreads();
        #pragma unroll
        for (int kk = 0; kk < 32; kk++) {
            float a[5], bb[8];
            #pragma unroll
            for (int i = 0; i < 5; i++) a[i] = As[kk][ty + 16*i];
            #pragma unroll
            for (int j = 0; j < 8; j++) bb[j] = Bs[kk][tx + 16*j];
            #pragma unroll
            for (int i = 0; i < 5; i++)
                #pragma unroll
                for (int j = 0; j < 8; j++) acc[i][j] += a[i]*bb[j];
        }
        __syncthreads();
    }
    float* P = g_part + (size_t)z*(RSZ*3072);
    #pragma unroll
    for (int i = 0; i < 5; i++)
        #pragma unroll
        for (int j = 0; j < 8; j++)
            P[(m0+ty+16*i)*3072 + n0 + tx + 16*j] = acc[i][j];
}

// grid 160 block 512
__global__ __launch_bounds__(512)
void k_gru_gate(const float* __restrict__ bih,
                const float* __restrict__ bhh, int parity) {
    const float* __restrict__ hold = parity ? g_hB : g_hA;
    float* __restrict__ hnew = parity ? g_hA : g_hB;
    int r = blockIdx.x, c = threadIdx.x;
    float ir=0.f, iz=0.f, inn=0.f, hr=0.f, hz=0.f, hn=0.f;
    #pragma unroll
    for (int z = 0; z < 4; z++) {
        const float* P = g_part + (size_t)z*(RSZ*3072) + (size_t)r*3072;
        ir += P[c]; iz += P[512+c]; inn += P[1024+c];
        hr += P[1536+c]; hz += P[2048+c]; hn += P[2560+c];
    }
    ir += bih[c]; iz += bih[512+c]; inn += bih[1024+c];
    hr += bhh[c]; hz += bhh[512+c]; hn += bhh[1024+c];
    float rg = 1.f/(1.f+expf(-(ir+hr)));
    float zg = 1.f/(1.f+expf(-(iz+hz)));
    float ng = tanhf(inn + rg*hn);
    hnew[r*HSZ+c] = (1.f-zg)*ng + zg*hold[r*HSZ+c];
}

// grid 16 block 512
__global__ __launch_bounds__(512)
void k_attn(const int* __restrict__ x, const float* __restrict__ enc,
            const float* __restrict__ wgenW, const float* __restrict__ wgenb,
            const float* __restrict__ actW, const float* __restrict__ actb,
            float* __restrict__ out, int is_t0, int parity) {
    const float* __restrict__ hnew = parity ? g_hA : g_hB;
    __shared__ float hs[JSZ][HSZ];
    __shared__ float attn[JSZ][SSZ];
    __shared__ int   xs[SSZ];
    int b = blockIdx.x, tid = threadIdx.x, warp = tid >> 5, lane = tid & 31;

    for (int i = tid; i < JSZ*HSZ; i += 512) {
        int j = i / HSZ, h = i - j*HSZ;
        hs[j][h] = hnew[(j*BSZ+b)*HSZ + h];
    }
    if (tid < SSZ) xs[tid] = x[b*SSZ + tid];
    __syncthreads();

    for (int s = warp; s < SSZ; s += 16) {
        const float4* ev = (const float4*)(enc + ((size_t)b*SSZ + s)*HSZ);
        float4 e0 = ev[lane], e1 = ev[lane+32], e2 = ev[lane+64], e3 = ev[lane+96];
        float accj[JSZ];
        #pragma unroll
        for (int j = 0; j < JSZ; j++) {
            const float4* hv = (const float4*)(&hs[j][0]);
            float4 h0 = hv[lane], h1 = hv[lane+32], h2 = hv[lane+64], h3 = hv[lane+96];
            accj[j] = e0.x*h0.x + e0.y*h0.y + e0.z*h0.z + e0.w*h0.w
                    + e1.x*h1.x + e1.y*h1.y + e1.z*h1.z + e1.w*h1.w
                    + e2.x*h2.x + e2.y*h2.y + e2.z*h2.z + e2.w*h2.w
                    + e3.x*h3.x + e3.y*h3.y + e3.z*h3.z + e3.w*h3.w;
        }
        #pragma unroll
        for (int j = 0; j < JSZ; j++) {
            float v = accj[j];
            #pragma unroll
            for (int off = 16; off > 0; off >>= 1)
                v += __shfl_xor_sync(0xffffffffu, v, off);
            accj[j] = v;
        }
        if (lane == 0)
            #pragma unroll
            for (int j = 0; j < JSZ; j++) attn[j][s] = accj[j];
    }
    __syncthreads();

    if (warp < JSZ) {
        int j = warp;
        float v[8]; float mx = -3.4e38f;
        #pragma unroll
        for (int k = 0; k < 8; k++) {
            int s = lane + 32*k;
            float sc = (xs[s] == 0) ? NEGV : attn[j][s];
            v[k] = sc; mx = fmaxf(mx, sc);
        }
        #pragma unroll
        for (int off = 16; off > 0; off >>= 1)
            mx = fmaxf(mx, __shfl_xor_sync(0xffffffffu, mx, off));
        float sm = 0.f;
        #pragma unroll
        for (int k = 0; k < 8; k++) { v[k] = expf(v[k]-mx); sm += v[k]; }
        #pragma unroll
        for (int off = 16; off > 0; off >>= 1)
            sm += __shfl_xor_sync(0xffffffffu, sm, off);
        float inv = 1.f/sm;
        int r = j*BSZ + b;
        #pragma unroll
        for (int k = 0; k < 8; k++) {
            int s = lane + 32*k;
            float a = v[k]*inv;
            attn[j][s] = a;
            g_attn[r*SSZ + s] = a;
        }
    }
    __syncthreads();

    for (int task = warp; task < 2*JSZ; task += 16) {
        int j = task >> 1; int hq = (task & 1) * 64;
        float4 c0 = make_float4(0,0,0,0), c1 = make_float4(0,0,0,0);
        const float4* eb = (const float4*)(enc + (size_t)b*SSZ*HSZ);
        #pragma unroll 4
        for (int s = 0; s < SSZ; s++) {
            float a = attn[j][s];
            const float4* e = eb + (size_t)s*(HSZ/4);
            float4 e0 = e[hq + lane], e1 = e[hq + lane + 32];
            c0.x += a*e0.x; c0.y += a*e0.y; c0.z += a*e0.z; c0.w += a*e0.w;
            c1.x += a*e1.x; c1.y += a*e1.y; c1.z += a*e1.z; c1.w += a*e1.w;
        }
        float4* cg = (float4*)(g_ctx + ((size_t)(j*BSZ+b))*HSZ);
        cg[hq + lane] = c0; cg[hq + lane + 32] = c1;
    }
    __syncthreads();

    if (warp < JSZ) {
        int j = warp, r = j*BSZ + b;
        float v = 0.f;
        for (int i = lane; i < HSZ; i += 32) {
            v += g_w[r*HSZ+i]   * wgenW[i];
            v += hs[j][i]       * wgenW[HSZ+i];
            v += g_ctx[r*HSZ+i] * wgenW[2*HSZ+i];
        }
        #pragma unroll
        for (int off = 16; off > 0; off >>= 1)
            v += __shfl_xor_sync(0xffffffffu, v, off);
        if (lane == 0) g_pgen[r] = 1.f/(1.f+expf(-(v + wgenb[0])));
    }

    if (is_t0) {
        for (int p = warp; p < JSZ*NOPS; p += 16) {
            int j = p / NOPS, op = p - j*NOPS, r = j*BSZ + b;
            float v = 0.f;
            for (int i = lane; i < HSZ; i += 32)
                v += g_ctx[r*HSZ+i] * actW[op*HSZ+i];
            #pragma unroll
            for (int off = 16; off > 0; off >>= 1)
                v += __shfl_xor_sync(0xffffffffu, v, off);
            if (lane == 0) out[b*JSZ*NOPS + j*NOPS + op] = v + actb[op];
        }
    }
}

// grid (235,2) block 256
__global__ __launch_bounds__(256)
void k_vocab_gemm(const float* __restrict__ emb, int parity) {
    const float* __restrict__ hnew = parity ? g_hA : g_hB;
    int n0 = blockIdx.x * 128, m0 = blockIdx.y * 80;
    __shared__ float As[32][81];
    __shared__ float Bs[32][129];
    int tid = threadIdx.x, tx = tid & 15, ty = tid >> 4;
    float acc[5][8];
    #pragma unroll
    for (int i = 0; i < 5; i++)
        #pragma unroll
        for (int j = 0; j < 8; j++) acc[i][j] = 0.f;
    for (int kt = 0; kt < 16; kt++) {
        int k0 = kt*32;
        #pragma unroll
        for (int i = 0; i < 10; i++) {
            int idx = tid + 256*i; int m = idx >> 5, kk = idx & 31;
            As[kk][m] = hnew[(m0+m)*HSZ + k0 + kk];
        }
        #pragma unroll
        for (int i = 0; i < 16; i++) {
            int idx = tid + 256*i; int n = idx >> 5, kk = idx & 31;
            int v = n0 + n;
            Bs[kk][n] = (v < VSZ) ? emb[(size_t)v*HSZ + k0 + kk] : 0.f;
        }
        __syncthreads();
        #pragma unroll
        for (int kk = 0; kk < 32; kk++) {
            float a[5], bb[8];
            #pragma unroll
            for (int i = 0; i < 5; i++) a[i] = As[kk][ty + 16*i];
            #pragma unroll
            for (int j = 0; j < 8; j++) bb[j] = Bs[kk][tx + 16*j];
            #pragma unroll
            for (int i = 0; i < 5; i++)
                #pragma unroll
                for (int j = 0; j < 8; j++) acc[i][j] += a[i]*bb[j];
        }
        __syncthreads();
    }
    #pragma unroll
    for (int i = 0; i < 5; i++) {
        int rr = m0 + ty + 16*i;
        #pragma unroll
        for (int j = 0; j < 8; j++) {
            int v = n0 + tx + 16*j;
            if (v < VSZ) g_logits[(size_t)rr*VSZ + v] = acc[i][j];
        }
    }
}

// grid 160 block 256
__global__ __launch_bounds__(256)
void k_softmax_out(float* __restrict__ out, int t, int ptoff) {
    int r = blockIdx.x, tid = threadIdx.x;
    int b = r % BSZ, j = r / BSZ;
    const float* __restrict__ L = g_logits + (size_t)r*VSZ;
    __shared__ float red[256];
    __shared__ float rv[256];
    __shared__ int   ri[256];
    float mx = -3.4e38f;
    for (int v = tid; v < VSZ; v += 256) mx = fmaxf(mx, L[v]);
    red[tid] = mx; __syncthreads();
    for (int off = 128; off > 0; off >>= 1) {
        if (tid < off) red[tid] = fmaxf(red[tid], red[tid+off]);
        __syncthreads();
    }
    mx = red[0]; __syncthreads();
    float sm = 0.f;
    for (int v = tid; v < VSZ; v += 256) sm += expf(L[v]-mx);
    red[tid] = sm; __syncthreads();
    for (int off = 128; off > 0; off >>= 1) {
        if (tid < off) red[tid] += red[tid+off];
        __syncthreads();
    }
    sm = red[0];
    float scale = g_pgen[r] / sm;
    float* ob = out + ptoff + ((size_t)(b*JSZ + j)*TSZ + t)*VSZ;
    float bestv = -1.f; int besti = 0;
    for (int v = tid; v < VSZ; v += 256) {
        float p = expf(L[v]-mx)*scale;
        ob[v] = p;
        if (p > bestv) { bestv = p; besti = v; }
    }
    rv[tid] = bestv; ri[tid] = besti; __syncthreads();
    for (int off = 128; off > 0; off >>= 1) {
        if (tid < off) {
            float ov = rv[tid+off]; int oi = ri[tid+off];
            if (ov > rv[tid] || (ov == rv[tid] && oi < ri[tid])) { rv[tid]=ov; ri[tid]=oi; }
        }
        __syncthreads();
    }
    if (tid == 0) { g_bval[r] = rv[0]; g_bidx[r] = ri[0]; }
}

// grid 160 block 256
__global__ __launch_bounds__(256)
void k_scatter(const int* __restrict__ x, float* __restrict__ out,
               int t, int ptoff) {
    int r = blockIdx.x, s = threadIdx.x;
    int b = r % BSZ, j = r / BSZ;
    float a = g_attn[r*SSZ + s];
    if (a != 0.f) {
        int v = x[b*SSZ + s];
        atomicAdd(out + ptoff + ((size_t)(b*JSZ + j)*TSZ + t)*VSZ + v, (1.f-g_pgen[r])*a);
    }
}

// grid 160 block 256
__global__ __launch_bounds__(256)
void k_argmax_next(const int* __restrict__ x, const float* __restrict__ emb,
                   const float* __restrict__ out, int t, int ptoff) {
    int r = blockIdx.x, tid = threadIdx.x;
    int b = r % BSZ, j = r / BSZ;
    const float* ob = out + ptoff + ((size_t)(b*JSZ + j)*TSZ + t)*VSZ;
    __shared__ float rv[256];
    __shared__ int   ri[256];
    __shared__ int   widx;
    int v = x[b*SSZ + tid];
    float bestv = ob[v]; int besti = v;
    if (tid == 0) {
        float bv = g_bval[r]; int bi = g_bidx[r];
        if (bv > bestv || (bv == bestv && bi < besti)) { bestv = bv; besti = bi; }
    }
    rv[tid] = bestv; ri[tid] = besti; __syncthreads();
    for (int off = 128; off > 0; off >>= 1) {
        if (tid < off) {
            float ov = rv[tid+off]; int oi = ri[tid+off];
            if (ov > rv[tid] || (ov == rv[tid] && oi < ri[tid])) { rv[tid]=ov; ri[tid]=oi; }
        }
        __syncthreads();
    }
    if (tid == 0) widx = ri[0];
    __syncthreads();
    for (int i = tid; i < HSZ; i += 256)
        g_w[r*HSZ + i] = emb[(size_t)widx*HSZ + i];
}

extern "C" void kernel_launch(void* const* d_in, const int* in_sizes, int n_in,
                              void* d_out, int out_size) {
    const int*   x     = (const int*)  d_in[0];
    const float* enc   = (const float*)d_in[1];
    const float* ehid  = (const float*)d_in[2];
    /* d_in[3] = max_len (known constant TSZ=8) */
    const float* emb   = (const float*)d_in[4];
    const float* slot  = (const float*)d_in[5];
    const float* Wih   = (const float*)d_in[6];
    const float* Whh   = (const float*)d_in[7];
    const float* bih   = (const float*)d_in[8];
    const float* bhh   = (const float*)d_in[9];
    const float* wgenW = (const float*)d_in[10];
    const float* wgenb = (const float*)d_in[11];
    const float* actW  = (const float*)d_in[12];
    const float* actb  = (const float*)d_in[13];
    float* out = (float*)d_out;
    const int ptoff = BSZ*JSZ*NOPS; // gates first, then points

    k_init<<<(RSZ*HSZ + 255)/256, 256>>>(slot, ehid);
    for (int t = 0; t < TSZ; t++) {
        int parity = t & 1;
        k_gru_gemm<<<dim3(24,2,4), 256>>>(Wih, Whh, parity);
        k_gru_gate<<<RSZ, 512>>>(bih, bhh, parity);
        k_attn<<<BSZ, 512>>>(x, enc, wgenW, wgenb, actW, actb, out, t == 0, parity);
        k_vocab_gemm<<<dim3(235,2), 256>>>(emb, parity);
        k_softmax_out<<<RSZ, 256>>>(out, t, ptoff);
        k_scatter<<<RSZ, 256>>>(x, out, t, ptoff);
        k_argmax_next<<<RSZ, 256>>>(x, emb, out, t, ptoff);
    }
}

// round 4
// speedup vs baseline: 1.3936x; 1.3936x over previous
#include <cuda_runtime.h>
#include <math.h>
#include <float.h>

#define VSZ 30000
#define HSZ 512
#define BSZ 16
#define SSZ 256
#define JSZ 10
#define TSZ 8
#define NOPS 4
#define RSZ (JSZ*BSZ)
#define NEGV (-1e9f)

__device__ float g_w[RSZ*HSZ];
__device__ float g_hA[RSZ*HSZ];
__device__ float g_hB[RSZ*HSZ];
__device__ float g_part[4*RSZ*3072];
__device__ float g_logits[RSZ*VSZ];
__device__ float g_attn[RSZ*SSZ];
__device__ float g_ctx[RSZ*HSZ];
__device__ float g_pgen[RSZ];

__global__ __launch_bounds__(256)
void k_init(const float* __restrict__ slot, const float* __restrict__ ehid) {
    int i = blockIdx.x*blockDim.x + threadIdx.x;
    if (i < RSZ*HSZ) {
        int r = i / HSZ, h = i - r*HSZ;
        int j = r / BSZ, b = r - j*BSZ;
        g_w[i]  = slot[j*HSZ + h];
        g_hA[i] = ehid[b*HSZ + h];
    }
}

// grid (24,2,4) block 256: P[r,n] n<1536: w@Wih^T else h@Whh^T, split-K=4
__global__ __launch_bounds__(256)
void k_gru_gemm(const float* __restrict__ Wih,
                const float* __restrict__ Whh, int parity) {
    const float* __restrict__ hold = parity ? g_hB : g_hA;
    int n0 = blockIdx.x * 128, m0 = blockIdx.y * 80, z = blockIdx.z;
    const float* __restrict__ A  = (n0 < 1536) ? g_w : hold;
    const float* __restrict__ Bm = (n0 < 1536) ? Wih : Whh;
    int bc0 = (n0 < 1536) ? n0 : (n0 - 1536);
    __shared__ float As[32][81];
    __shared__ float Bs[32][129];
    int tid = threadIdx.x, tx = tid & 15, ty = tid >> 4;
    float acc[5][8];
    #pragma unroll
    for (int i = 0; i < 5; i++)
        #pragma unroll
        for (int j = 0; j < 8; j++) acc[i][j] = 0.f;
    for (int kt = 0; kt < 4; kt++) {
        int k0 = z*128 + kt*32;
        #pragma unroll
        for (int i = 0; i < 10; i++) {
            int idx = tid + 256*i; int m = idx >> 5, kk = idx & 31;
            As[kk][m] = A[(m0+m)*HSZ + k0 + kk];
        }
        #pragma unroll
        for (int i = 0; i < 16; i++) {
            int idx = tid + 256*i; int n = idx >> 5, kk = idx & 31;
            Bs[kk][n] = Bm[(bc0+n)*HSZ + k0 + kk];
        }
        __syncthreads();
        #pragma unroll
        for (int kk = 0; kk < 32; kk++) {
            float a[5], bb[8];
            #pragma unroll
            for (int i = 0; i < 5; i++) a[i] = As[kk][ty + 16*i];
            #pragma unroll
            for (int j = 0; j < 8; j++) bb[j] = Bs[kk][tx + 16*j];
            #pragma unroll
            for (int i = 0; i < 5; i++)
                #pragma unroll
                for (int j = 0; j < 8; j++) acc[i][j] += a[i]*bb[j];
        }
        __syncthreads();
    }
    float* P = g_part + (size_t)z*(RSZ*3072);
    #pragma unroll
    for (int i = 0; i < 5; i++)
        #pragma unroll
        for (int j = 0; j < 8; j++)
            P[(m0+ty+16*i)*3072 + n0 + tx + 16*j] = acc[i][j];
}

// grid 160 block 512
__global__ __launch_bounds__(512)
void k_gru_gate(const float* __restrict__ bih,
                const float* __restrict__ bhh, int parity) {
    const float* __restrict__ hold = parity ? g_hB : g_hA;
    float* __restrict__ hnew = parity ? g_hA : g_hB;
    int r = blockIdx.x, c = threadIdx.x;
    float ir=0.f, iz=0.f, inn=0.f, hr=0.f, hz=0.f, hn=0.f;
    #pragma unroll
    for (int z = 0; z < 4; z++) {
        const float* P = g_part + (size_t)z*(RSZ*3072) + (size_t)r*3072;
        ir += P[c]; iz += P[512+c]; inn += P[1024+c];
        hr += P[1536+c]; hz += P[2048+c]; hn += P[2560+c];
    }
    ir += bih[c]; iz += bih[512+c]; inn += bih[1024+c];
    hr += bhh[c]; hz += bhh[512+c]; hn += bhh[1024+c];
    float rg = 1.f/(1.f+expf(-(ir+hr)));
    float zg = 1.f/(1.f+expf(-(iz+hz)));
    float ng = tanhf(inn + rg*hn);
    hnew[r*HSZ+c] = (1.f-zg)*ng + zg*hold[r*HSZ+c];
}

// grid 160 (one block per r = j*BSZ+b), block 512
__global__ __launch_bounds__(512)
void k_attn(const int* __restrict__ x, const float* __restrict__ enc,
            const float* __restrict__ wgenW, const float* __restrict__ wgenb,
            const float* __restrict__ actW, const float* __restrict__ actb,
            float* __restrict__ out, int is_t0, int parity) {
    const float* __restrict__ hnew = parity ? g_hA : g_hB;
    int r = blockIdx.x, tid = threadIdx.x, lane = tid & 31, warp = tid >> 5;
    int j = r / BSZ, b = r % BSZ;
    __shared__ float hs[HSZ];
    __shared__ float att[SSZ];
    __shared__ int   xs[SSZ];
    __shared__ float red[512];

    hs[tid] = hnew[(size_t)r*HSZ + tid];
    if (tid < SSZ) xs[tid] = x[b*SSZ + tid];
    __syncthreads();

    // scores: warp w handles s in [w*16, w*16+16)
    const float4* hv = (const float4*)hs;
    float4 h0 = hv[lane], h1 = hv[lane+32], h2 = hv[lane+64], h3 = hv[lane+96];
    #pragma unroll 4
    for (int i = 0; i < 16; i++) {
        int s = warp*16 + i;
        const float4* ev = (const float4*)(enc + ((size_t)b*SSZ + s)*HSZ);
        float4 e0 = ev[lane], e1 = ev[lane+32], e2 = ev[lane+64], e3 = ev[lane+96];
        float v = e0.x*h0.x + e0.y*h0.y + e0.z*h0.z + e0.w*h0.w
                + e1.x*h1.x + e1.y*h1.y + e1.z*h1.z + e1.w*h1.w
                + e2.x*h2.x + e2.y*h2.y + e2.z*h2.z + e2.w*h2.w
                + e3.x*h3.x + e3.y*h3.y + e3.z*h3.z + e3.w*h3.w;
        #pragma unroll
        for (int off = 16; off > 0; off >>= 1)
            v += __shfl_xor_sync(0xffffffffu, v, off);
        if (lane == 0) att[s] = (xs[s] == 0) ? NEGV : v;
    }
    __syncthreads();

    // block softmax over S=256
    float mv = (tid < SSZ) ? att[tid] : -FLT_MAX;
    red[tid] = mv; __syncthreads();
    #pragma unroll
    for (int off = 256; off > 0; off >>= 1) {
        if (tid < off) red[tid] = fmaxf(red[tid], red[tid+off]);
        __syncthreads();
    }
    float mx = red[0]; __syncthreads();
    float ex = (tid < SSZ) ? expf(mv - mx) : 0.f;
    red[tid] = ex; __syncthreads();
    #pragma unroll
    for (int off = 256; off > 0; off >>= 1) {
        if (tid < off) red[tid] += red[tid+off];
        __syncthreads();
    }
    float inv = 1.f/red[0]; __syncthreads();
    if (tid < SSZ) {
        float a = ex*inv;
        att[tid] = a;
        g_attn[r*SSZ + tid] = a;
    }
    __syncthreads();

    // context: thread tid owns column tid
    float ctx = 0.f;
    const float* eb = enc + (size_t)b*SSZ*HSZ + tid;
    #pragma unroll 8
    for (int s = 0; s < SSZ; s++) ctx += att[s]*eb[(size_t)s*HSZ];
    g_ctx[(size_t)r*HSZ + tid] = ctx;

    // p_gen
    float pv = g_w[(size_t)r*HSZ+tid]*wgenW[tid]
             + hs[tid]*wgenW[HSZ+tid]
             + ctx*wgenW[2*HSZ+tid];
    red[tid] = pv; __syncthreads();
    #pragma unroll
    for (int off = 256; off > 0; off >>= 1) {
        if (tid < off) red[tid] += red[tid+off];
        __syncthreads();
    }
    if (tid == 0) g_pgen[r] = 1.f/(1.f+expf(-(red[0] + wgenb[0])));

    // gate head at t==0
    if (is_t0) {
        #pragma unroll
        for (int op = 0; op < NOPS; op++) {
            __syncthreads();
            red[tid] = ctx*actW[op*HSZ + tid]; __syncthreads();
            #pragma unroll
            for (int off = 256; off > 0; off >>= 1) {
                if (tid < off) red[tid] += red[tid+off];
                __syncthreads();
            }
            if (tid == 0) out[b*JSZ*NOPS + j*NOPS + op] = red[0] + actb[op];
        }
    }
}

// grid (235,2) block 256
__global__ __launch_bounds__(256)
void k_vocab_gemm(const float* __restrict__ emb, int parity) {
    const float* __restrict__ hnew = parity ? g_hA : g_hB;
    int n0 = blockIdx.x * 128, m0 = blockIdx.y * 80;
    __shared__ float As[32][81];
    __shared__ float Bs[32][129];
    int tid = threadIdx.x, tx = tid & 15, ty = tid >> 4;
    float acc[5][8];
    #pragma unroll
    for (int i = 0; i < 5; i++)
        #pragma unroll
        for (int j = 0; j < 8; j++) acc[i][j] = 0.f;
    for (int kt = 0; kt < 16; kt++) {
        int k0 = kt*32;
        #pragma unroll
        for (int i = 0; i < 10; i++) {
            int idx = tid + 256*i; int m = idx >> 5, kk = idx & 31;
            As[kk][m] = hnew[(m0+m)*HSZ + k0 + kk];
        }
        #pragma unroll
        for (int i = 0; i < 16; i++) {
            int idx = tid + 256*i; int n = idx >> 5, kk = idx & 31;
            int v = n0 + n;
            Bs[kk][n] = (v < VSZ) ? emb[(size_t)v*HSZ + k0 + kk] : 0.f;
        }
        __syncthreads();
        #pragma unroll
        for (int kk = 0; kk < 32; kk++) {
            float a[5], bb[8];
            #pragma unroll
            for (int i = 0; i < 5; i++) a[i] = As[kk][ty + 16*i];
            #pragma unroll
            for (int j = 0; j < 8; j++) bb[j] = Bs[kk][tx + 16*j];
            #pragma unroll
            for (int i = 0; i < 5; i++)
                #pragma unroll
                for (int j = 0; j < 8; j++) acc[i][j] += a[i]*bb[j];
        }
        __syncthreads();
    }
    #pragma unroll
    for (int i = 0; i < 5; i++) {
        int rr = m0 + ty + 16*i;
        #pragma unroll
        for (int j = 0; j < 8; j++) {
            int v = n0 + tx + 16*j;
            if (v < VSZ) g_logits[(size_t)rr*VSZ + v] = acc[i][j];
        }
    }
}

// grid 160 block 512: softmax + base write + base argmax + scatter + final argmax + next-w
__global__ __launch_bounds__(512)
void k_softmax_fused(const int* __restrict__ x, const float* __restrict__ emb,
                     float* __restrict__ out, int t, int ptoff) {
    int r = blockIdx.x, tid = threadIdx.x;
    int b = r % BSZ, j = r / BSZ;
    const float* __restrict__ L = g_logits + (size_t)r*VSZ;
    const float4* __restrict__ L4 = (const float4*)L;
    __shared__ float red[512];
    __shared__ int   redi[512];
    __shared__ float s_bv;
    __shared__ int   s_bi;
    __shared__ int   s_widx;

    // pass 1: max
    float mx = -FLT_MAX;
    for (int i = tid; i < VSZ/4; i += 512) {
        float4 q = L4[i];
        mx = fmaxf(mx, fmaxf(fmaxf(q.x, q.y), fmaxf(q.z, q.w)));
    }
    red[tid] = mx; __syncthreads();
    #pragma unroll
    for (int off = 256; off > 0; off >>= 1) {
        if (tid < off) red[tid] = fmaxf(red[tid], red[tid+off]);
        __syncthreads();
    }
    mx = red[0]; __syncthreads();

    // pass 2: sum
    float sm = 0.f;
    for (int i = tid; i < VSZ/4; i += 512) {
        float4 q = L4[i];
        sm += expf(q.x-mx) + expf(q.y-mx) + expf(q.z-mx) + expf(q.w-mx);
    }
    red[tid] = sm; __syncthreads();
    #pragma unroll
    for (int off = 256; off > 0; off >>= 1) {
        if (tid < off) red[tid] += red[tid+off];
        __syncthreads();
    }
    sm = red[0]; __syncthreads();

    float pg = g_pgen[r];
    float scale = pg / sm;
    float* ob = out + ptoff + ((size_t)(b*JSZ + j)*TSZ + t)*VSZ;
    float4* ob4 = (float4*)ob;

    // pass 3: write base p, track base argmax (lowest index on ties via strict >
    // with increasing index order per thread)
    float bv = -1.f; int bi = 0;
    for (int i = tid; i < VSZ/4; i += 512) {
        float4 q = L4[i];
        float4 p;
        p.x = expf(q.x-mx)*scale; p.y = expf(q.y-mx)*scale;
        p.z = expf(q.z-mx)*scale; p.w = expf(q.w-mx)*scale;
        ob4[i] = p;
        if (p.x > bv) { bv = p.x; bi = 4*i; }
        if (p.y > bv) { bv = p.y; bi = 4*i+1; }
        if (p.z > bv) { bv = p.z; bi = 4*i+2; }
        if (p.w > bv) { bv = p.w; bi = 4*i+3; }
    }
    red[tid] = bv; redi[tid] = bi; __syncthreads();
    #pragma unroll
    for (int off = 256; off > 0; off >>= 1) {
        if (tid < off) {
            float ov = red[tid+off]; int oi = redi[tid+off];
            if (ov > red[tid] || (ov == red[tid] && oi < redi[tid])) {
                red[tid] = ov; redi[tid] = oi;
            }
        }
        __syncthreads();
    }
    if (tid == 0) { s_bv = red[0]; s_bi = redi[0]; }
    __threadfence();
    __syncthreads();   // base writes visible block-wide before atomics

    // scatter pointer mass
    int vv = 0; float a = 0.f;
    if (tid < SSZ) {
        a = g_attn[r*SSZ + tid];
        if (a != 0.f) {
            vv = x[b*SSZ + tid];
            atomicAdd(ob + vv, (1.f - pg)*a);
        }
    }
    __threadfence();
    __syncthreads();   // all scatters complete

    // final argmax: scattered candidates via L2-coherent read-back + base candidate
    float cv = -1.f; int ci = 0x7fffffff;
    if (tid < SSZ && a != 0.f) {
        cv = atomicAdd(ob + vv, 0.f);   // coherent read (bypasses L1)
        ci = vv;
    }
    red[tid] = cv; redi[tid] = ci; __syncthreads();
    #pragma unroll
    for (int off = 256; off > 0; off >>= 1) {
        if (tid < off) {
            float ov = red[tid+off]; int oi = redi[tid+off];
            if (ov > red[tid] || (ov == red[tid] && oi < redi[tid])) {
                red[tid] = ov; redi[tid] = oi;
            }
        }
        __syncthreads();
    }
    if (tid == 0) {
        float fv = red[0]; int fi = redi[0];
        if (s_bv > fv || (s_bv == fv && s_bi < fi)) { fv = s_bv; fi = s_bi; }
        s_widx = fi;
    }
    __syncthreads();
    int widx = s_widx;
    g_w[(size_t)r*HSZ + tid] = emb[(size_t)widx*HSZ + tid];
}

extern "C" void kernel_launch(void* const* d_in, const int* in_sizes, int n_in,
                              void* d_out, int out_size) {
    const int*   x     = (const int*)  d_in[0];
    const float* enc   = (const float*)d_in[1];
    const float* ehid  = (const float*)d_in[2];
    /* d_in[3] = max_len (constant TSZ=8) */
    const float* emb   = (const float*)d_in[4];
    const float* slot  = (const float*)d_in[5];
    const float* Wih   = (const float*)d_in[6];
    const float* Whh   = (const float*)d_in[7];
    const float* bih   = (const float*)d_in[8];
    const float* bhh   = (const float*)d_in[9];
    const float* wgenW = (const float*)d_in[10];
    const float* wgenb = (const float*)d_in[11];
    const float* actW  = (const float*)d_in[12];
    const float* actb  = (const float*)d_in[13];
    float* out = (float*)d_out;
    const int ptoff = BSZ*JSZ*NOPS;

    k_init<<<(RSZ*HSZ + 255)/256, 256>>>(slot, ehid);
    for (int t = 0; t < TSZ; t++) {
        int parity = t & 1;
        k_gru_gemm<<<dim3(24,2,4), 256>>>(Wih, Whh, parity);
        k_gru_gate<<<RSZ, 512>>>(bih, bhh, parity);
        k_attn<<<RSZ, 512>>>(x, enc, wgenW, wgenb, actW, actb, out, t == 0, parity);
        k_vocab_gemm<<<dim3(235,2), 256>>>(emb, parity);
        k_softmax_fused<<<RSZ, 512>>>(x, emb, out, t, ptoff);
    }
}

// round 7
// speedup vs baseline: 2.6682x; 1.9146x over previous
#include <cuda_runtime.h>
#include <cuda_bf16.h>
#include <mma.h>
#include <cstdint>
#include <cstddef>
#include <math.h>
#include <float.h>

using namespace nvcuda;

#define VSZ 30000
#define VPAD 30080
#define HSZ 512
#define BSZ 16
#define SSZ 256
#define JSZ 10
#define TSZ 8
#define NOPS 4
#define RSZ (JSZ*BSZ)
#define NEGV (-1e9f)

// fp32 state
__device__ float g_w[RSZ*HSZ];
__device__ float g_hA[RSZ*HSZ];
__device__ float g_hB[RSZ*HSZ];
__device__ float g_part[4*RSZ*3072];
__device__ float g_logits[RSZ*VSZ];
__device__ float g_attn[RSZ*SSZ];
__device__ float g_ctx[RSZ*HSZ];
__device__ float g_pgen[RSZ];
// bf16 hi/lo splits for tensor-core vocab GEMM
__device__ __nv_bfloat16 g_ehi[(size_t)VPAD*HSZ];
__device__ __nv_bfloat16 g_elo[(size_t)VPAD*HSZ];
__device__ __nv_bfloat16 g_hh[RSZ*HSZ];
__device__ __nv_bfloat16 g_hl[RSZ*HSZ];

// ---------------- cp.async helpers (sm_80 baseline ISA) ----------------
__device__ __forceinline__ uint32_t smem_to_u32(const void* smem_ptr) {
    uint32_t addr;
    asm("{ .reg .u64 tmp; cvta.to.shared.u64 tmp, %1; cvt.u32.u64 %0, tmp; }"
        : "=r"(addr) : "l"(smem_ptr));
    return addr;
}
__device__ __forceinline__ void cp_async16(uint32_t saddr, const void* gptr) {
    asm volatile("cp.async.cg.shared.global [%0], [%1], 16;"
                 :: "r"(saddr), "l"(gptr) : "memory");
}
#define CP_COMMIT() asm volatile("cp.async.commit_group;" ::: "memory")
#define CP_WAIT0()  asm volatile("cp.async.wait_group 0;" ::: "memory")

// ---------------- init ----------------
__global__ __launch_bounds__(256)
void k_init(const float* __restrict__ slot, const float* __restrict__ ehid) {
    int i = blockIdx.x*blockDim.x + threadIdx.x;
    if (i < RSZ*HSZ) {
        int r = i / HSZ, h = i - r*HSZ;
        int j = r / BSZ, b = r - j*BSZ;
        g_w[i]  = slot[j*HSZ + h];
        g_hA[i] = ehid[b*HSZ + h];
    }
}

// split emb into bf16 hi/lo, pad rows >= VSZ with zero
__global__ __launch_bounds__(256)
void k_split_emb(const float* __restrict__ emb) {
    size_t i = (size_t)blockIdx.x*blockDim.x + threadIdx.x;
    if (i >= (size_t)VPAD*HSZ) return;
    size_t row = i / HSZ;
    float v = (row < VSZ) ? emb[i] : 0.f;
    __nv_bfloat16 hi = __float2bfloat16_rn(v);
    float lo = v - __bfloat162float(hi);
    g_ehi[i] = hi;
    g_elo[i] = __float2bfloat16_rn(lo);
}

// ---------------- GRU GEMM (split-K=4) ----------------
__global__ __launch_bounds__(256)
void k_gru_gemm(const float* __restrict__ Wih,
                const float* __restrict__ Whh, int parity) {
    const float* __restrict__ hold = parity ? g_hB : g_hA;
    int n0 = blockIdx.x * 128, m0 = blockIdx.y * 80, z = blockIdx.z;
    const float* __restrict__ A  = (n0 < 1536) ? g_w : hold;
    const float* __restrict__ Bm = (n0 < 1536) ? Wih : Whh;
    int bc0 = (n0 < 1536) ? n0 : (n0 - 1536);
    __shared__ float As[32][81];
    __shared__ float Bs[32][129];
    int tid = threadIdx.x, tx = tid & 15, ty = tid >> 4;
    float acc[5][8];
    #pragma unroll
    for (int i = 0; i < 5; i++)
        #pragma unroll
        for (int j = 0; j < 8; j++) acc[i][j] = 0.f;
    for (int kt = 0; kt < 4; kt++) {
        int k0 = z*128 + kt*32;
        #pragma unroll
        for (int i = 0; i < 10; i++) {
            int idx = tid + 256*i; int m = idx >> 5, kk = idx & 31;
            As[kk][m] = A[(m0+m)*HSZ + k0 + kk];
        }
        #pragma unroll
        for (int i = 0; i < 16; i++) {
            int idx = tid + 256*i; int n = idx >> 5, kk = idx & 31;
            Bs[kk][n] = Bm[(bc0+n)*HSZ + k0 + kk];
        }
        __syncthreads();
        #pragma unroll
        for (int kk = 0; kk < 32; kk++) {
            float a[5], bb[8];
            #pragma unroll
            for (int i = 0; i < 5; i++) a[i] = As[kk][ty + 16*i];
            #pragma unroll
            for (int j = 0; j < 8; j++) bb[j] = Bs[kk][tx + 16*j];
            #pragma unroll
            for (int i = 0; i < 5; i++)
                #pragma unroll
                for (int j = 0; j < 8; j++) acc[i][j] += a[i]*bb[j];
        }
        __syncthreads();
    }
    float* P = g_part + (size_t)z*(RSZ*3072);
    #pragma unroll
    for (int i = 0; i < 5; i++)
        #pragma unroll
        for (int j = 0; j < 8; j++)
            P[(m0+ty+16*i)*3072 + n0 + tx + 16*j] = acc[i][j];
}

// ---------------- GRU gate + h bf16 split ----------------
__global__ __launch_bounds__(512)
void k_gru_gate(const float* __restrict__ bih,
                const float* __restrict__ bhh, int parity) {
    const float* __restrict__ hold = parity ? g_hB : g_hA;
    float* __restrict__ hnew = parity ? g_hA : g_hB;
    int r = blockIdx.x, c = threadIdx.x;
    float ir=0.f, iz=0.f, inn=0.f, hr=0.f, hz=0.f, hn=0.f;
    #pragma unroll
    for (int z = 0; z < 4; z++) {
        const float* P = g_part + (size_t)z*(RSZ*3072) + (size_t)r*3072;
        ir += P[c]; iz += P[512+c]; inn += P[1024+c];
        hr += P[1536+c]; hz += P[2048+c]; hn += P[2560+c];
    }
    ir += bih[c]; iz += bih[512+c]; inn += bih[1024+c];
    hr += bhh[c]; hz += bhh[512+c]; hn += bhh[1024+c];
    float rg = 1.f/(1.f+expf(-(ir+hr)));
    float zg = 1.f/(1.f+expf(-(iz+hz)));
    float ng = tanhf(inn + rg*hn);
    float v = (1.f-zg)*ng + zg*hold[r*HSZ+c];
    hnew[r*HSZ+c] = v;
    __nv_bfloat16 hi = __float2bfloat16_rn(v);
    float lo = v - __bfloat162float(hi);
    g_hh[r*HSZ+c] = hi;
    g_hl[r*HSZ+c] = __float2bfloat16_rn(lo);
}

// ---------------- attention + context + p_gen (+t0 gates) ----------------
__global__ __launch_bounds__(512)
void k_attn(const int* __restrict__ x, const float* __restrict__ enc,
            const float* __restrict__ wgenW, const float* __restrict__ wgenb,
            const float* __restrict__ actW, const float* __restrict__ actb,
            float* __restrict__ out, int is_t0, int parity) {
    const float* __restrict__ hnew = parity ? g_hA : g_hB;
    int r = blockIdx.x, tid = threadIdx.x, lane = tid & 31, warp = tid >> 5;
    int j = r / BSZ, b = r % BSZ;
    __shared__ float hs[HSZ];
    __shared__ float att[SSZ];
    __shared__ int   xs[SSZ];
    __shared__ float red[512];

    hs[tid] = hnew[(size_t)r*HSZ + tid];
    if (tid < SSZ) xs[tid] = x[b*SSZ + tid];
    __syncthreads();

    const float4* hv = (const float4*)hs;
    float4 h0 = hv[lane], h1 = hv[lane+32], h2 = hv[lane+64], h3 = hv[lane+96];
    #pragma unroll 4
    for (int i = 0; i < 16; i++) {
        int s = warp*16 + i;
        const float4* ev = (const float4*)(enc + ((size_t)b*SSZ + s)*HSZ);
        float4 e0 = ev[lane], e1 = ev[lane+32], e2 = ev[lane+64], e3 = ev[lane+96];
        float v = e0.x*h0.x + e0.y*h0.y + e0.z*h0.z + e0.w*h0.w
                + e1.x*h1.x + e1.y*h1.y + e1.z*h1.z + e1.w*h1.w
                + e2.x*h2.x + e2.y*h2.y + e2.z*h2.z + e2.w*h2.w
                + e3.x*h3.x + e3.y*h3.y + e3.z*h3.z + e3.w*h3.w;
        #pragma unroll
        for (int off = 16; off > 0; off >>= 1)
            v += __shfl_xor_sync(0xffffffffu, v, off);
        if (lane == 0) att[s] = (xs[s] == 0) ? NEGV : v;
    }
    __syncthreads();

    float mv = (tid < SSZ) ? att[tid] : -FLT_MAX;
    red[tid] = mv; __syncthreads();
    #pragma unroll
    for (int off = 256; off > 0; off >>= 1) {
        if (tid < off) red[tid] = fmaxf(red[tid], red[tid+off]);
        __syncthreads();
    }
    float mx = red[0]; __syncthreads();
    float ex = (tid < SSZ) ? expf(mv - mx) : 0.f;
    red[tid] = ex; __syncthreads();
    #pragma unroll
    for (int off = 256; off > 0; off >>= 1) {
        if (tid < off) red[tid] += red[tid+off];
        __syncthreads();
    }
    float inv = 1.f/red[0]; __syncthreads();
    if (tid < SSZ) {
        float a = ex*inv;
        att[tid] = a;
        g_attn[r*SSZ + tid] = a;
    }
    __syncthreads();

    float ctx = 0.f;
    const float* eb = enc + (size_t)b*SSZ*HSZ + tid;
    #pragma unroll 8
    for (int s = 0; s < SSZ; s++) ctx += att[s]*eb[(size_t)s*HSZ];
    g_ctx[(size_t)r*HSZ + tid] = ctx;

    float pv = g_w[(size_t)r*HSZ+tid]*wgenW[tid]
             + hs[tid]*wgenW[HSZ+tid]
             + ctx*wgenW[2*HSZ+tid];
    red[tid] = pv; __syncthreads();
    #pragma unroll
    for (int off = 256; off > 0; off >>= 1) {
        if (tid < off) red[tid] += red[tid+off];
        __syncthreads();
    }
    if (tid == 0) g_pgen[r] = 1.f/(1.f+expf(-(red[0] + wgenb[0])));

    if (is_t0) {
        #pragma unroll
        for (int op = 0; op < NOPS; op++) {
            __syncthreads();
            red[tid] = ctx*actW[op*HSZ + tid]; __syncthreads();
            #pragma unroll
            for (int off = 256; off > 0; off >>= 1) {
                if (tid < off) red[tid] += red[tid+off];
                __syncthreads();
            }
            if (tid == 0) out[b*JSZ*NOPS + j*NOPS + op] = red[0] + actb[op];
        }
    }
}

// ---------------- wmma bf16 vocab GEMM (baseline-ISA tensor cores) --------
// grid 235, block 256 (8 warps). CTA tile: 128 v-rows x 160 h-rows, K=512.
// Warp grid 4x2: warp tile 32 v x 80 n. hi/lo 3-pass. cp.async double buffer.
#define KC 64
#define LDA 72
#define A_SPL (128*LDA*2)          /* 18432 B per split */
#define B_SPL (160*LDA*2)          /* 23040 B per split */
#define OFF_AHI 0
#define OFF_ALO (A_SPL)
#define OFF_BHI (2*A_SPL)
#define OFF_BLO (2*A_SPL + B_SPL)
#define SBUF    (2*A_SPL + 2*B_SPL) /* 82944 B */
#define VW_SMEM (2*SBUF)            /* 165888 B */

__global__ __launch_bounds__(256)
void k_vocab_wmma() {
    extern __shared__ char smem[];
    uint32_t sb = smem_to_u32(smem);
    int tid = threadIdx.x, wid = tid >> 5;
    int wr = wid >> 1, wc = wid & 1;           // 4 x 2 warp grid
    size_t vbase = (size_t)blockIdx.x * 128;

    const uint4* Ehi = (const uint4*)g_ehi;
    const uint4* Elo = (const uint4*)g_elo;
    const uint4* Hhi = (const uint4*)g_hh;
    const uint4* Hlo = (const uint4*)g_hl;

    wmma::fragment<wmma::accumulator, 16, 16, 16, float> acc[2][5];
    #pragma unroll
    for (int i = 0; i < 2; i++)
        #pragma unroll
        for (int j = 0; j < 5; j++) wmma::fill_fragment(acc[i][j], 0.f);

    // issue chunk 0 loads
    {
        uint32_t base = sb;
        #pragma unroll
        for (int it = 0; it < 4; it++) {        // A: 1024 uint4 per split
            int idx = tid + 256*it;
            int row = idx >> 3, q = idx & 7;
            uint32_t so = (uint32_t)(row*LDA + q*8) * 2u;
            size_t gi = (vbase + (size_t)row) * 64 + (size_t)q;
            cp_async16(base + OFF_AHI + so, Ehi + gi);
            cp_async16(base + OFF_ALO + so, Elo + gi);
        }
        #pragma unroll
        for (int it = 0; it < 5; it++) {        // B: 1280 uint4 per split
            int idx = tid + 256*it;
            if (idx < 1280) {
                int row = idx >> 3, q = idx & 7;
                uint32_t so = (uint32_t)(row*LDA + q*8) * 2u;
                size_t gi = (size_t)row * 64 + (size_t)q;
                cp_async16(base + OFF_BHI + so, Hhi + gi);
                cp_async16(base + OFF_BLO + so, Hlo + gi);
            }
        }
        CP_COMMIT();
    }

    for (int c = 0; c < 8; c++) {
        CP_WAIT0();
        __syncthreads();
        if (c < 7) {
            uint32_t base = sb + ((c + 1) & 1) * SBUF;
            int cq = (c + 1) * 8;
            #pragma unroll
            for (int it = 0; it < 4; it++) {
                int idx = tid + 256*it;
                int row = idx >> 3, q = idx & 7;
                uint32_t so = (uint32_t)(row*LDA + q*8) * 2u;
                size_t gi = (vbase + (size_t)row) * 64 + (size_t)(cq + q);
                cp_async16(base + OFF_AHI + so, Ehi + gi);
                cp_async16(base + OFF_ALO + so, Elo + gi);
            }
            #pragma unroll
            for (int it = 0; it < 5; it++) {
                int idx = tid + 256*it;
                if (idx < 1280) {
                    int row = idx >> 3, q = idx & 7;
                    uint32_t so = (uint32_t)(row*LDA + q*8) * 2u;
                    size_t gi = (size_t)row * 64 + (size_t)(cq + q);
                    cp_async16(base + OFF_BHI + so, Hhi + gi);
                    cp_async16(base + OFF_BLO + so, Hlo + gi);
                }
            }
            CP_COMMIT();
        }
        const __nv_bfloat16* pAhi = (const __nv_bfloat16*)(smem + (c & 1)*SBUF + OFF_AHI);
        const __nv_bfloat16* pAlo = (const __nv_bfloat16*)(smem + (c & 1)*SBUF + OFF_ALO);
        const __nv_bfloat16* pBhi = (const __nv_bfloat16*)(smem + (c & 1)*SBUF + OFF_BHI);
        const __nv_bfloat16* pBlo = (const __nv_bfloat16*)(smem + (c & 1)*SBUF + OFF_BLO);
        #pragma unroll
        for (int kk = 0; kk < 4; kk++) {
            wmma::fragment<wmma::matrix_a, 16, 16, 16, __nv_bfloat16, wmma::row_major> a0h, a1h, a0l, a1l;
            wmma::load_matrix_sync(a0h, pAhi + (wr*32)      * LDA + kk*16, LDA);
            wmma::load_matrix_sync(a1h, pAhi + (wr*32 + 16) * LDA + kk*16, LDA);
            wmma::load_matrix_sync(a0l, pAlo + (wr*32)      * LDA + kk*16, LDA);
            wmma::load_matrix_sync(a1l, pAlo + (wr*32 + 16) * LDA + kk*16, LDA);
            #pragma unroll
            for (int j = 0; j < 5; j++) {
                int nb = wc*80 + j*16;
                wmma::fragment<wmma::matrix_b, 16, 16, 16, __nv_bfloat16, wmma::col_major> bh, bl;
                wmma::load_matrix_sync(bh, pBhi + nb*LDA + kk*16, LDA);
                wmma::mma_sync(acc[0][j], a0h, bh, acc[0][j]);
                wmma::mma_sync(acc[1][j], a1h, bh, acc[1][j]);
                wmma::mma_sync(acc[0][j], a0l, bh, acc[0][j]);
                wmma::mma_sync(acc[1][j], a1l, bh, acc[1][j]);
                wmma::load_matrix_sync(bl, pBlo + nb*LDA + kk*16, LDA);
                wmma::mma_sync(acc[0][j], a0h, bl, acc[0][j]);
                wmma::mma_sync(acc[1][j], a1h, bl, acc[1][j]);
            }
        }
        __syncthreads();
    }

    // store: D[m=v][n=r] -> g_logits[r*VSZ + v]  (col-major store, ldm=VSZ)
    #pragma unroll
    for (int i = 0; i < 2; i++) {
        size_t v0 = vbase + (size_t)(wr*32 + i*16);
        if (v0 < VSZ) {
            #pragma unroll
            for (int j = 0; j < 5; j++) {
                int n0 = wc*80 + j*16;
                wmma::store_matrix_sync(g_logits + (size_t)n0*VSZ + v0,
                                        acc[i][j], VSZ, wmma::mem_col_major);
            }
        }
    }
}

// ---------------- fused softmax + output + scatter + argmax + next-w ------
__global__ __launch_bounds__(512)
void k_softmax_fused(const int* __restrict__ x, const float* __restrict__ emb,
                     float* __restrict__ out, int t, int ptoff) {
    int r = blockIdx.x, tid = threadIdx.x;
    int b = r % BSZ, j = r / BSZ;
    const float* __restrict__ L = g_logits + (size_t)r*VSZ;
    const float4* __restrict__ L4 = (const float4*)L;
    __shared__ float red[512];
    __shared__ int   redi[512];
    __shared__ float s_bv;
    __shared__ int   s_bi;
    __shared__ int   s_widx;

    float mx = -FLT_MAX;
    for (int i = tid; i < VSZ/4; i += 512) {
        float4 q = L4[i];
        mx = fmaxf(mx, fmaxf(fmaxf(q.x, q.y), fmaxf(q.z, q.w)));
    }
    red[tid] = mx; __syncthreads();
    #pragma unroll
    for (int off = 256; off > 0; off >>= 1) {
        if (tid < off) red[tid] = fmaxf(red[tid], red[tid+off]);
        __syncthreads();
    }
    mx = red[0]; __syncthreads();

    float sm = 0.f;
    for (int i = tid; i < VSZ/4; i += 512) {
        float4 q = L4[i];
        sm += expf(q.x-mx) + expf(q.y-mx) + expf(q.z-mx) + expf(q.w-mx);
    }
    red[tid] = sm; __syncthreads();
    #pragma unroll
    for (int off = 256; off > 0; off >>= 1) {
        if (tid < off) red[tid] += red[tid+off];
        __syncthreads();
    }
    sm = red[0]; __syncthreads();

    float pg = g_pgen[r];
    float scale = pg / sm;
    float* ob = out + ptoff + ((size_t)(b*JSZ + j)*TSZ + t)*VSZ;
    float4* ob4 = (float4*)ob;

    float bv = -1.f; int bi = 0;
    for (int i = tid; i < VSZ/4; i += 512) {
        float4 q = L4[i];
        float4 p;
        p.x = expf(q.x-mx)*scale; p.y = expf(q.y-mx)*scale;
        p.z = expf(q.z-mx)*scale; p.w = expf(q.w-mx)*scale;
        ob4[i] = p;
        if (p.x > bv) { bv = p.x; bi = 4*i; }
        if (p.y > bv) { bv = p.y; bi = 4*i+1; }
        if (p.z > bv) { bv = p.z; bi = 4*i+2; }
        if (p.w > bv) { bv = p.w; bi = 4*i+3; }
    }
    red[tid] = bv; redi[tid] = bi; __syncthreads();
    #pragma unroll
    for (int off = 256; off > 0; off >>= 1) {
        if (tid < off) {
            float ov = red[tid+off]; int oi = redi[tid+off];
            if (ov > red[tid] || (ov == red[tid] && oi < redi[tid])) {
                red[tid] = ov; redi[tid] = oi;
            }
        }
        __syncthreads();
    }
    if (tid == 0) { s_bv = red[0]; s_bi = redi[0]; }
    __threadfence();
    __syncthreads();

    int vv = 0; float a = 0.f;
    if (tid < SSZ) {
        a = g_attn[r*SSZ + tid];
        if (a != 0.f) {
            vv = x[b*SSZ + tid];
            atomicAdd(ob + vv, (1.f - pg)*a);
        }
    }
    __threadfence();
    __syncthreads();

    float cv = -1.f; int ci = 0x7fffffff;
    if (tid < SSZ && a != 0.f) {
        cv = atomicAdd(ob + vv, 0.f);
        ci = vv;
    }
    red[tid] = cv; redi[tid] = ci; __syncthreads();
    #pragma unroll
    for (int off = 256; off > 0; off >>= 1) {
        if (tid < off) {
            float ov = red[tid+off]; int oi = redi[tid+off];
            if (ov > red[tid] || (ov == red[tid] && oi < redi[tid])) {
                red[tid] = ov; redi[tid] = oi;
            }
        }
        __syncthreads();
    }
    if (tid == 0) {
        float fv = red[0]; int fi = redi[0];
        if (s_bv > fv || (s_bv == fv && s_bi < fi)) { fv = s_bv; fi = s_bi; }
        s_widx = fi;
    }
    __syncthreads();
    int widx = s_widx;
    g_w[(size_t)r*HSZ + tid] = emb[(size_t)widx*HSZ + tid];
}

extern "C" void kernel_launch(void* const* d_in, const int* in_sizes, int n_in,
                              void* d_out, int out_size) {
    const int*   x     = (const int*)  d_in[0];
    const float* enc   = (const float*)d_in[1];
    const float* ehid  = (const float*)d_in[2];
    /* d_in[3] = max_len (constant TSZ=8) */
    const float* emb   = (const float*)d_in[4];
    const float* slot  = (const float*)d_in[5];
    const float* Wih   = (const float*)d_in[6];
    const float* Whh   = (const float*)d_in[7];
    const float* bih   = (const float*)d_in[8];
    const float* bhh   = (const float*)d_in[9];
    const float* wgenW = (const float*)d_in[10];
    const float* wgenb = (const float*)d_in[11];
    const float* actW  = (const float*)d_in[12];
    const float* actb  = (const float*)d_in[13];
    float* out = (float*)d_out;
    const int ptoff = BSZ*JSZ*NOPS;

    cudaFuncSetAttribute(k_vocab_wmma, cudaFuncAttributeMaxDynamicSharedMemorySize, VW_SMEM);

    k_init<<<(RSZ*HSZ + 255)/256, 256>>>(slot, ehid);
    k_split_emb<<<(int)(((size_t)VPAD*HSZ + 255)/256), 256>>>(emb);
    for (int t = 0; t < TSZ; t++) {
        int parity = t & 1;
        k_gru_gemm<<<dim3(24,2,4), 256>>>(Wih, Whh, parity);
        k_gru_gate<<<RSZ, 512>>>(bih, bhh, parity);
        k_attn<<<RSZ, 512>>>(x, enc, wgenW, wgenb, actW, actb, out, t == 0, parity);
        k_vocab_wmma<<<235, 256, VW_SMEM>>>();
        k_softmax_fused<<<RSZ, 512>>>(x, emb, out, t, ptoff);
    }
}